// round 3
// baseline (speedup 1.0000x reference)
#include <cuda_runtime.h>
#include <math.h>

// Problem constants (from reference): POS_DIM=288, N_FREQS=12, MARGIN=0.2,
// INVALID_VALUE=-0.1. Shapes: B=128, C=273, T=2048, O=270, S=200.
#define POS_DIM 288
#define NFREQ   12

// Scratch (no cudaMalloc allowed): emb [B*C, 288] and scores/weights [B, O, C]
__device__ float g_emb[128 * 273 * 288];   // ~40.2 MB
__device__ float g_sc [128 * 270 * 273];   // ~37.7 MB

// ---------------------------------------------------------------------------
// Kernel 1: Fourier embedding. One block per (b,c) row, 144 threads.
// emb[row, j]      = cos(loc_j)
// emb[row, 144+j]  = sin(loc_j),  loc_j = (px+m)*w*fi + (py+m)*w*fj
// ---------------------------------------------------------------------------
__global__ void emb_kernel(const float* __restrict__ pos, int BC) {
    int row = blockIdx.x;
    if (row >= BC) return;
    int j = threadIdx.x;                    // 0..143
    float px = pos[2 * row]     + 0.2f;
    float py = pos[2 * row + 1] + 0.2f;
    const float w = 6.283185307179586f / 1.4f;   // 2*pi / (1 + 2*margin)
    int fi = j / NFREQ;
    int fj = j - fi * NFREQ;
    float loc = px * (w * (float)fi) + py * (w * (float)fj);
    float s, c;
    sincosf(loc, &s, &c);
    size_t base = (size_t)row * POS_DIM;
    g_emb[base + j]       = c;
    g_emb[base + 144 + j] = s;
}

// ---------------------------------------------------------------------------
// Kernel 2: scores[b,o,c] = sum_d emb[b,c,d] * heads[sid[b],o,d]
// Per-b GEMM, both operands K-major. 64x64 tile, BK=16, 4x4 per thread.
// Tiles stored K-transposed in smem (stride 68 floats = 272B, 16B aligned
// so float4 reads stay legal; 68 mod 32 = 4 keeps STS conflicts to 2-way).
// ---------------------------------------------------------------------------
__global__ __launch_bounds__(256)
void scores_kernel(const float* __restrict__ heads, const int* __restrict__ sid,
                   int B, int C, int O) {
    __shared__ float Hs[16][68];   // [k][o]
    __shared__ float Es[16][68];   // [k][c]
    int b  = blockIdx.z;
    int o0 = blockIdx.y * 64;
    int c0 = blockIdx.x * 64;
    int tid = threadIdx.x;
    int tx = tid & 15, ty = tid >> 4;
    const float* hb = heads + (size_t)sid[b] * O * POS_DIM;
    const float* eb = g_emb + (size_t)b * C * POS_DIM;

    float acc[4][4] = {};
    for (int k0 = 0; k0 < POS_DIM; k0 += 16) {
        #pragma unroll
        for (int e = 0; e < 4; e++) {
            int li = tid + e * 256;          // 0..1023
            int r = li >> 4, k = li & 15;
            Hs[k][r] = (o0 + r < O) ? hb[(size_t)(o0 + r) * POS_DIM + k0 + k] : 0.f;
            Es[k][r] = (c0 + r < C) ? eb[(size_t)(c0 + r) * POS_DIM + k0 + k] : 0.f;
        }
        __syncthreads();
        #pragma unroll
        for (int k = 0; k < 16; k++) {
            float4 a4 = *(const float4*)&Hs[k][ty * 4];
            float4 b4 = *(const float4*)&Es[k][tx * 4];
            float av[4] = {a4.x, a4.y, a4.z, a4.w};
            float bv[4] = {b4.x, b4.y, b4.z, b4.w};
            #pragma unroll
            for (int i = 0; i < 4; i++)
                #pragma unroll
                for (int jj = 0; jj < 4; jj++)
                    acc[i][jj] += av[i] * bv[jj];
        }
        __syncthreads();
    }
    #pragma unroll
    for (int i = 0; i < 4; i++) {
        int go = o0 + ty * 4 + i;
        if (go >= O) continue;
        float* dst = g_sc + ((size_t)b * O + go) * C;
        #pragma unroll
        for (int jj = 0; jj < 4; jj++) {
            int gc = c0 + tx * 4 + jj;
            if (gc < C) dst[gc] = acc[i][jj];
        }
    }
}

// ---------------------------------------------------------------------------
// Kernel 3: masked softmax over C for each (b,o) row. One warp per row,
// row cached in registers (ceil(273/32)=9 per lane).
// ---------------------------------------------------------------------------
__global__ void softmax_kernel(const float* __restrict__ pos,
                               int B, int C, int O, int rows) {
    int gwarp = (blockIdx.x * blockDim.x + threadIdx.x) >> 5;
    int lane  = threadIdx.x & 31;
    if (gwarp >= rows) return;
    int b = gwarp / O;
    float* row = g_sc + (size_t)gwarp * C;
    const float* pb = pos + (size_t)b * C * 2;

    float v[9];
    float mx = -INFINITY;
    #pragma unroll
    for (int i = 0; i < 9; i++) {
        int c = lane + i * 32;
        float val = -INFINITY;
        if (c < C) {
            val = row[c];
            float px = pb[2 * c], py = pb[2 * c + 1];
            if (px == -0.1f && py == -0.1f) val = -INFINITY;  // invalid channel
        }
        v[i] = val;
        mx = fmaxf(mx, val);
    }
    #pragma unroll
    for (int s = 16; s > 0; s >>= 1)
        mx = fmaxf(mx, __shfl_xor_sync(0xffffffffu, mx, s));

    float sum = 0.f;
    #pragma unroll
    for (int i = 0; i < 9; i++) {
        float e = expf(v[i] - mx);     // expf(-inf - finite) = 0
        v[i] = e;
        sum += (lane + i * 32 < C) ? e : 0.f;
    }
    #pragma unroll
    for (int s = 16; s > 0; s >>= 1)
        sum += __shfl_xor_sync(0xffffffffu, sum, s);
    float inv = 1.f / sum;

    #pragma unroll
    for (int i = 0; i < 9; i++) {
        int c = lane + i * 32;
        if (c < C) row[c] = v[i] * inv;
    }
}

// ---------------------------------------------------------------------------
// Kernel 4 (dominant): out[b,o,t] = sum_c W[b,o,c] * meg[b,c,t]
// Per-b GEMM: M=O=270, N=T=2048, K=C=273. Tile 64(o) x 128(t) x 16(k),
// 256 threads, 4x8 micro-tile -> 32 FFMA per 3 float4 LDS -> FFMA-bound.
// ---------------------------------------------------------------------------
__global__ __launch_bounds__(256)
void out_kernel(const float* __restrict__ meg, float* __restrict__ out,
                int B, int C, int T, int O) {
    __shared__ float Ws[16][68];    // [k][o], padded stride
    __shared__ float Ms[16][128];   // [k][t]
    int b  = blockIdx.z;
    int o0 = blockIdx.y * 64;
    int t0 = blockIdx.x * 128;
    int tid = threadIdx.x;
    int tx = tid & 15, ty = tid >> 4;
    const float* mb = meg  + (size_t)b * C * T;
    const float* wb = g_sc + (size_t)b * O * C;

    float acc[4][8] = {};
    for (int k0 = 0; k0 < C; k0 += 16) {
        #pragma unroll
        for (int e = 0; e < 4; e++) {
            int li = tid + e * 256;          // 0..1023
            int o = li >> 4, k = li & 15;
            float v = 0.f;
            if (o0 + o < O && k0 + k < C) v = wb[(size_t)(o0 + o) * C + k0 + k];
            Ws[k][o] = v;
        }
        #pragma unroll
        for (int e = 0; e < 8; e++) {
            int li = tid + e * 256;          // 0..2047
            int t = li & 127, k = li >> 7;
            Ms[k][t] = (k0 + k < C) ? mb[(size_t)(k0 + k) * T + t0 + t] : 0.f;
        }
        __syncthreads();
        #pragma unroll
        for (int k = 0; k < 16; k++) {
            float4 a4 = *(const float4*)&Ws[k][ty * 4];
            float4 b0 = *(const float4*)&Ms[k][tx * 4];
            float4 b1 = *(const float4*)&Ms[k][64 + tx * 4];
            float av[4] = {a4.x, a4.y, a4.z, a4.w};
            float bv[8] = {b0.x, b0.y, b0.z, b0.w, b1.x, b1.y, b1.z, b1.w};
            #pragma unroll
            for (int i = 0; i < 4; i++)
                #pragma unroll
                for (int jj = 0; jj < 8; jj++)
                    acc[i][jj] += av[i] * bv[jj];
        }
        __syncthreads();
    }
    #pragma unroll
    for (int i = 0; i < 4; i++) {
        int go = o0 + ty * 4 + i;
        if (go >= O) continue;
        float* dst = out + ((size_t)b * O + go) * T + t0 + tx * 4;
        *(float4*)(dst)      = make_float4(acc[i][0], acc[i][1], acc[i][2], acc[i][3]);
        *(float4*)(dst + 64) = make_float4(acc[i][4], acc[i][5], acc[i][6], acc[i][7]);
    }
}

// ---------------------------------------------------------------------------
// Launch. Inputs (metadata order): meg f32 [B,C,T], positions f32 [B,C,2],
// subject_ids i32 [B], heads f32 [S,O,POS_DIM]. Output f32 [B,O,T].
// ---------------------------------------------------------------------------
extern "C" void kernel_launch(void* const* d_in, const int* in_sizes, int n_in,
                              void* d_out, int out_size) {
    const float* meg   = (const float*)d_in[0];
    const float* pos   = (const float*)d_in[1];
    const int*   sid   = (const int*)  d_in[2];
    const float* heads = (const float*)d_in[3];
    float* out = (float*)d_out;

    int B = in_sizes[2];
    int C = in_sizes[1] / (2 * B);
    int T = in_sizes[0] / (B * C);
    int O = out_size / (B * T);

    // 1) Fourier embedding
    emb_kernel<<<B * C, 144>>>(pos, B * C);

    // 2) scores = emb @ heads[sid]^T
    dim3 gs((C + 63) / 64, (O + 63) / 64, B);
    scores_kernel<<<gs, 256>>>(heads, sid, B, C, O);

    // 3) masked softmax over channels
    int rows = B * O;
    int nblk = (rows * 32 + 255) / 256;
    softmax_kernel<<<nblk, 256>>>(pos, B, C, O, rows);

    // 4) out = weights @ meg
    dim3 gd((T + 127) / 128, (O + 63) / 64, B);
    out_kernel<<<gd, 256>>>(meg, out, B, C, T, O);
}

// round 6
// speedup vs baseline: 2.4589x; 2.4589x over previous
#include <cuda_runtime.h>
#include <math.h>
#include <stdint.h>

#define POS_DIM 288
#define NFREQ   12
#define CP      288      // padded pitch for weights rows (16B-aligned)
#define BM      128
#define BN      128
#define BK      32
#define AP      36       // A smem pitch (floats), conflict-free fragment reads
#define BP      132      // meg smem pitch (floats), conflict-free fragment reads

// Scratch (no cudaMalloc allowed)
__device__ float g_emb[128 * 273 * 288];   // [B*C, 288]
__device__ float g_sc [128 * 270 * CP];    // [B, O, CP] scores -> weights

// ---------------------------------------------------------------------------
// helpers
// ---------------------------------------------------------------------------
__device__ __forceinline__ uint32_t smem_u32(const void* p) {
    uint32_t a;
    asm("{ .reg .u64 t; cvta.to.shared.u64 t, %1; cvt.u32.u64 %0, t; }"
        : "=r"(a) : "l"(p));
    return a;
}
__device__ __forceinline__ void cp16(const void* dst, const void* src, bool full) {
    uint32_t d = smem_u32(dst);
    int sz = full ? 16 : 0;
    asm volatile("cp.async.cg.shared.global [%0], [%1], 16, %2;"
                 :: "r"(d), "l"(src), "r"(sz) : "memory");
}
#define CP_COMMIT() asm volatile("cp.async.commit_group;" ::: "memory")
#define CP_WAIT1()  asm volatile("cp.async.wait_group 1;" ::: "memory")
#define CP_WAIT0()  asm volatile("cp.async.wait_group 0;" ::: "memory")

__device__ __forceinline__ uint32_t f2tf(float x) {   // round-to-nearest tf32
    uint32_t r;
    asm("cvt.rna.tf32.f32 %0, %1;" : "=r"(r) : "f"(x));
    return r;
}

__device__ __forceinline__ void mma8(float c[4], const uint32_t a[4], const uint32_t b[2]) {
    asm volatile(
        "mma.sync.aligned.m16n8k8.row.col.f32.tf32.tf32.f32 "
        "{%0,%1,%2,%3}, {%4,%5,%6,%7}, {%8,%9}, {%0,%1,%2,%3};"
        : "+f"(c[0]), "+f"(c[1]), "+f"(c[2]), "+f"(c[3])
        : "r"(a[0]), "r"(a[1]), "r"(a[2]), "r"(a[3]), "r"(b[0]), "r"(b[1]));
}

// ---------------------------------------------------------------------------
// Kernel 1: Fourier embedding
// ---------------------------------------------------------------------------
__global__ void emb_kernel(const float* __restrict__ pos, int BC) {
    int row = blockIdx.x;
    if (row >= BC) return;
    int j = threadIdx.x;                    // 0..143
    float px = pos[2 * row]     + 0.2f;
    float py = pos[2 * row + 1] + 0.2f;
    const float w = 6.283185307179586f / 1.4f;
    int fi = j / NFREQ;
    int fj = j - fi * NFREQ;
    float loc = px * (w * (float)fi) + py * (w * (float)fj);
    float s, c;
    sincosf(loc, &s, &c);
    size_t base = (size_t)row * POS_DIM;
    g_emb[base + j]       = c;
    g_emb[base + 144 + j] = s;
}

// ---------------------------------------------------------------------------
// Kernel 2: scores[b,o,c] = sum_d heads[sid[b],o,d] * emb[b,c,d]
// Split-tf32 (hi/lo, 3 MMAs) -> near-fp32 accuracy for the softmax input.
// ---------------------------------------------------------------------------
__global__ __launch_bounds__(256, 2)
void scores_mma(const float* __restrict__ heads, const int* __restrict__ sid,
                int B_, int C, int O) {
    extern __shared__ float sm[];
    float* As = sm;                 // [2][128][36]
    float* Es = sm + 2 * BM * AP;   // [2][128][36]

    int tid = threadIdx.x, wid = tid >> 5, lane = tid & 31;
    int g = lane >> 2, tig = lane & 3;
    int b = blockIdx.z, o0 = blockIdx.y * BM, c0 = blockIdx.x * BN;
    int mi = (wid >> 2) * 64, ni = (wid & 3) * 32;

    const float* hb = heads + (size_t)sid[b] * O * POS_DIM;
    const float* eb = g_emb + (size_t)b * C * POS_DIM;

    float acc[4][4][4] = {};
    const int nch = POS_DIM / BK;   // 9

    auto load = [&](int j, int buf) {
        int k0 = j * BK;
        float* A = As + buf * BM * AP;
        float* E = Es + buf * BM * AP;
        #pragma unroll
        for (int r = 0; r < 4; r++) {
            int idx = tid + r * 256;
            int m = idx >> 3, k4 = (idx & 7) * 4;
            int go = o0 + m;
            cp16(A + m * AP + k4,
                 hb + (size_t)(go < O ? go : 0) * POS_DIM + k0 + k4, go < O);
            int gc = c0 + m;
            cp16(E + m * AP + k4,
                 eb + (size_t)(gc < C ? gc : 0) * POS_DIM + k0 + k4, gc < C);
        }
        CP_COMMIT();
    };

    load(0, 0);
    for (int j = 0; j < nch; j++) {
        int buf = j & 1;
        if (j + 1 < nch) { load(j + 1, buf ^ 1); CP_WAIT1(); }
        else             { CP_WAIT0(); }
        __syncthreads();
        const float* A = As + buf * BM * AP;
        const float* E = Es + buf * BM * AP;
        #pragma unroll
        for (int kk = 0; kk < BK; kk += 8) {
            uint32_t ah[4][4], al[4][4];
            #pragma unroll
            for (int mt = 0; mt < 4; mt++) {
                const float* ap = A + (mi + mt * 16 + g) * AP + kk + tig;
                float x0 = ap[0], x1 = ap[8 * AP], x2 = ap[4], x3 = ap[8 * AP + 4];
                ah[mt][0] = f2tf(x0); al[mt][0] = f2tf(x0 - __uint_as_float(ah[mt][0]));
                ah[mt][1] = f2tf(x1); al[mt][1] = f2tf(x1 - __uint_as_float(ah[mt][1]));
                ah[mt][2] = f2tf(x2); al[mt][2] = f2tf(x2 - __uint_as_float(ah[mt][2]));
                ah[mt][3] = f2tf(x3); al[mt][3] = f2tf(x3 - __uint_as_float(ah[mt][3]));
            }
            #pragma unroll
            for (int nt = 0; nt < 4; nt++) {
                const float* bp = E + (ni + nt * 8 + g) * AP + kk + tig;
                float y0 = bp[0], y1 = bp[4];
                uint32_t bh[2], bl[2];
                bh[0] = f2tf(y0); bl[0] = f2tf(y0 - __uint_as_float(bh[0]));
                bh[1] = f2tf(y1); bl[1] = f2tf(y1 - __uint_as_float(bh[1]));
                #pragma unroll
                for (int mt = 0; mt < 4; mt++) {
                    mma8(acc[mt][nt], ah[mt], bh);
                    mma8(acc[mt][nt], ah[mt], bl);
                    mma8(acc[mt][nt], al[mt], bh);
                }
            }
        }
        __syncthreads();
    }

    float* outb = g_sc + (size_t)b * O * CP;
    #pragma unroll
    for (int mt = 0; mt < 4; mt++) {
        int r0 = o0 + mi + mt * 16 + g;
        int r1 = r0 + 8;
        #pragma unroll
        for (int nt = 0; nt < 4; nt++) {
            int gc = c0 + ni + nt * 8 + tig * 2;
            if (gc < CP) {
                if (r0 < O)
                    *(float2*)(outb + (size_t)r0 * CP + gc) =
                        make_float2(acc[mt][nt][0], acc[mt][nt][1]);
                if (r1 < O)
                    *(float2*)(outb + (size_t)r1 * CP + gc) =
                        make_float2(acc[mt][nt][2], acc[mt][nt][3]);
            }
        }
    }
}

// ---------------------------------------------------------------------------
// Kernel 3: masked softmax over C; zero-fills weight cols [C, CP).
// ---------------------------------------------------------------------------
__global__ void softmax_kernel(const float* __restrict__ pos,
                               int B_, int C, int O, int rows) {
    int gwarp = (blockIdx.x * blockDim.x + threadIdx.x) >> 5;
    int lane  = threadIdx.x & 31;
    if (gwarp >= rows) return;
    int b = gwarp / O;
    float* row = g_sc + (size_t)gwarp * CP;
    const float* pb = pos + (size_t)b * C * 2;

    float v[9];
    float mx = -INFINITY;
    #pragma unroll
    for (int i = 0; i < 9; i++) {
        int c = lane + i * 32;
        float val = -INFINITY;
        if (c < C) {
            val = row[c];
            float px = pb[2 * c], py = pb[2 * c + 1];
            if (px == -0.1f && py == -0.1f) val = -INFINITY;
        }
        v[i] = val;
        mx = fmaxf(mx, val);
    }
    #pragma unroll
    for (int s = 16; s > 0; s >>= 1)
        mx = fmaxf(mx, __shfl_xor_sync(0xffffffffu, mx, s));

    float sum = 0.f;
    #pragma unroll
    for (int i = 0; i < 9; i++) {
        float e = expf(v[i] - mx);
        v[i] = e;
        sum += (lane + i * 32 < C) ? e : 0.f;
    }
    #pragma unroll
    for (int s = 16; s > 0; s >>= 1)
        sum += __shfl_xor_sync(0xffffffffu, sum, s);
    float inv = 1.f / sum;

    #pragma unroll
    for (int i = 0; i < 9; i++) {
        int c = lane + i * 32;
        if (c < C)       row[c] = v[i] * inv;
        else if (c < CP) row[c] = 0.f;       // pad -> exact zeros for GEMM
    }
}

// ---------------------------------------------------------------------------
// Kernel 4 (dominant): out[b,o,t] = sum_c W[b,o,c] * meg[b,c,t]
// tf32 mma.sync with rna rounding. B = meg [c][t] = (k,n) -> .col fragment
// directly, no transpose. 9 full K-chunks (A zero-padded to 288 by softmax,
// meg rows >= C zero-filled by cp.async).
// ---------------------------------------------------------------------------
__global__ __launch_bounds__(256, 2)
void out_mma(const float* __restrict__ meg, float* __restrict__ out,
             int B_, int C, int T, int O) {
    extern __shared__ float sm[];
    float* As = sm;                 // [2][128][36]
    float* Bs = sm + 2 * BM * AP;   // [2][32][132]

    int tid = threadIdx.x, wid = tid >> 5, lane = tid & 31;
    int g = lane >> 2, tig = lane & 3;
    int b = blockIdx.z, o0 = blockIdx.y * BM, t0 = blockIdx.x * BN;
    int mi = (wid >> 2) * 64, ni = (wid & 3) * 32;

    const float* wb = g_sc + (size_t)b * O * CP;
    const float* mb = meg  + (size_t)b * C * T;

    float acc[4][4][4] = {};
    const int nch = CP / BK;   // 9

    auto load = [&](int j, int buf) {
        int k0 = j * BK;
        float* A  = As + buf * BM * AP;
        float* Bt = Bs + buf * BK * BP;
        // A: 128 x 32 weights (pitch CP, 16B-aligned rows): 4*256 cp16
        #pragma unroll
        for (int r = 0; r < 4; r++) {
            int idx = tid + r * 256;
            int m = idx >> 3, k4 = (idx & 7) * 4;
            int go = o0 + m;
            cp16(A + m * AP + k4,
                 wb + (size_t)(go < O ? go : 0) * CP + k0 + k4, go < O);
        }
        // B: 32 x 128 meg rows: 4*256 cp16 (FIX: full 32 k-rows)
        #pragma unroll
        for (int r = 0; r < 4; r++) {
            int idx = tid + r * 256;          // 0..1023
            int c = idx >> 5, t4 = (idx & 31) * 4;
            int gc = k0 + c;
            cp16(Bt + c * BP + t4,
                 mb + (size_t)(gc < C ? gc : 0) * T + t0 + t4, gc < C);
        }
        CP_COMMIT();
    };

    load(0, 0);
    for (int j = 0; j < nch; j++) {
        int buf = j & 1;
        if (j + 1 < nch) { load(j + 1, buf ^ 1); CP_WAIT1(); }
        else             { CP_WAIT0(); }
        __syncthreads();
        const float* A  = As + buf * BM * AP;
        const float* Bt = Bs + buf * BK * BP;
        #pragma unroll
        for (int kk = 0; kk < BK; kk += 8) {
            uint32_t a[4][4], bf[4][2];
            #pragma unroll
            for (int mt = 0; mt < 4; mt++) {
                const float* ap = A + (mi + mt * 16 + g) * AP + kk + tig;
                a[mt][0] = f2tf(ap[0]);
                a[mt][1] = f2tf(ap[8 * AP]);
                a[mt][2] = f2tf(ap[4]);
                a[mt][3] = f2tf(ap[8 * AP + 4]);
            }
            #pragma unroll
            for (int nt = 0; nt < 4; nt++) {
                const float* bp = Bt + (kk + tig) * BP + ni + nt * 8 + g;
                bf[nt][0] = f2tf(bp[0]);
                bf[nt][1] = f2tf(bp[4 * BP]);
            }
            #pragma unroll
            for (int mt = 0; mt < 4; mt++)
                #pragma unroll
                for (int nt = 0; nt < 4; nt++)
                    mma8(acc[mt][nt], a[mt], bf[nt]);
        }
        __syncthreads();
    }

    #pragma unroll
    for (int mt = 0; mt < 4; mt++) {
        int r0 = o0 + mi + mt * 16 + g;
        int r1 = r0 + 8;
        #pragma unroll
        for (int nt = 0; nt < 4; nt++) {
            int col = t0 + ni + nt * 8 + tig * 2;
            if (r0 < O)
                *(float2*)(out + ((size_t)b * O + r0) * T + col) =
                    make_float2(acc[mt][nt][0], acc[mt][nt][1]);
            if (r1 < O)
                *(float2*)(out + ((size_t)b * O + r1) * T + col) =
                    make_float2(acc[mt][nt][2], acc[mt][nt][3]);
        }
    }
}

// ---------------------------------------------------------------------------
// Launch. Inputs: meg f32 [B,C,T], positions f32 [B,C,2], subject_ids i32 [B],
// heads f32 [S,O,288]. Output f32 [B,O,T].
// ---------------------------------------------------------------------------
extern "C" void kernel_launch(void* const* d_in, const int* in_sizes, int n_in,
                              void* d_out, int out_size) {
    const float* meg   = (const float*)d_in[0];
    const float* pos   = (const float*)d_in[1];
    const int*   sid   = (const int*)  d_in[2];
    const float* heads = (const float*)d_in[3];
    float* out = (float*)d_out;

    int B = in_sizes[2];
    int C = in_sizes[1] / (2 * B);
    int T = in_sizes[0] / (B * C);
    int O = out_size / (B * T);

    const int smem_sc  = 2 * BM * AP * 4 + 2 * BM * AP * 4;   // 73728 B
    const int smem_out = 2 * BM * AP * 4 + 2 * BK * BP * 4;   // 70656 B
    cudaFuncSetAttribute(scores_mma, cudaFuncAttributeMaxDynamicSharedMemorySize, smem_sc);
    cudaFuncSetAttribute(out_mma,    cudaFuncAttributeMaxDynamicSharedMemorySize, smem_out);

    // 1) Fourier embedding
    emb_kernel<<<B * C, 144>>>(pos, B * C);

    // 2) scores = heads[sid] @ emb^T  (split-tf32 mma.sync)
    dim3 gs((C + BN - 1) / BN, (O + BM - 1) / BM, B);
    scores_mma<<<gs, 256, smem_sc>>>(heads, sid, B, C, O);

    // 3) masked softmax over channels (+ zero pad to CP)
    int rows = B * O;
    int nblk = (rows * 32 + 255) / 256;
    softmax_kernel<<<nblk, 256>>>(pos, B, C, O, rows);

    // 4) out = weights @ meg  (tf32 mma.sync, rna-rounded)
    dim3 gd(T / BN, (O + BM - 1) / BM, B);
    out_mma<<<gd, 256, smem_out>>>(meg, out, B, C, T, O);
}

// round 7
// speedup vs baseline: 2.6181x; 1.0648x over previous
#include <cuda_runtime.h>
#include <math.h>
#include <stdint.h>

#define POS_DIM 288
#define NFREQ   12
#define CP      288      // padded pitch for weights rows (16B-aligned)
#define BM      128
#define BN      128
#define BK      32
#define AP      36       // K-major smem pitch: ldmatrix + scalar reads conflict-free
#define BP      136      // meg smem pitch: 136 % 32 == 8 -> bank = 8*tig+g, bijective

// Scratch (no cudaMalloc allowed)
__device__ float g_emb[128 * 273 * 288];   // [B*C, 288]
__device__ float g_sc [128 * 270 * CP];    // [B, O, CP] scores -> tf32-rounded weights

// ---------------------------------------------------------------------------
// helpers
// ---------------------------------------------------------------------------
__device__ __forceinline__ uint32_t smem_u32(const void* p) {
    uint32_t a;
    asm("{ .reg .u64 t; cvta.to.shared.u64 t, %1; cvt.u32.u64 %0, t; }"
        : "=r"(a) : "l"(p));
    return a;
}
__device__ __forceinline__ void cp16(const void* dst, const void* src, bool full) {
    uint32_t d = smem_u32(dst);
    int sz = full ? 16 : 0;
    asm volatile("cp.async.cg.shared.global [%0], [%1], 16, %2;"
                 :: "r"(d), "l"(src), "r"(sz) : "memory");
}
#define CP_COMMIT() asm volatile("cp.async.commit_group;" ::: "memory")
#define CP_WAIT1()  asm volatile("cp.async.wait_group 1;" ::: "memory")
#define CP_WAIT0()  asm volatile("cp.async.wait_group 0;" ::: "memory")

__device__ __forceinline__ uint32_t f2tf(float x) {   // round-to-nearest tf32
    uint32_t r;
    asm("cvt.rna.tf32.f32 %0, %1;" : "=r"(r) : "f"(x));
    return r;
}
__device__ __forceinline__ void ldsm4(uint32_t r[4], uint32_t addr) {
    asm volatile("ldmatrix.sync.aligned.m8n8.x4.shared.b16 {%0,%1,%2,%3}, [%4];"
                 : "=r"(r[0]), "=r"(r[1]), "=r"(r[2]), "=r"(r[3]) : "r"(addr));
}
__device__ __forceinline__ void mma8(float c[4], const uint32_t a[4], const uint32_t b[2]) {
    asm volatile(
        "mma.sync.aligned.m16n8k8.row.col.f32.tf32.tf32.f32 "
        "{%0,%1,%2,%3}, {%4,%5,%6,%7}, {%8,%9}, {%0,%1,%2,%3};"
        : "+f"(c[0]), "+f"(c[1]), "+f"(c[2]), "+f"(c[3])
        : "r"(a[0]), "r"(a[1]), "r"(a[2]), "r"(a[3]), "r"(b[0]), "r"(b[1]));
}

// ---------------------------------------------------------------------------
// Kernel 1: Fourier embedding
// ---------------------------------------------------------------------------
__global__ void emb_kernel(const float* __restrict__ pos, int BC) {
    int row = blockIdx.x;
    if (row >= BC) return;
    int j = threadIdx.x;                    // 0..143
    float px = pos[2 * row]     + 0.2f;
    float py = pos[2 * row + 1] + 0.2f;
    const float w = 6.283185307179586f / 1.4f;
    int fi = j / NFREQ;
    int fj = j - fi * NFREQ;
    float loc = px * (w * (float)fi) + py * (w * (float)fj);
    float s, c;
    sincosf(loc, &s, &c);
    size_t base = (size_t)row * POS_DIM;
    g_emb[base + j]       = c;
    g_emb[base + 144 + j] = s;
}

// ---------------------------------------------------------------------------
// Kernel 2: scores[b,o,c] = sum_d heads[sid[b],o,d] * emb[b,c,d]
// Split-tf32 (hi/lo, 3 MMAs). Raw fragments via ldmatrix, hi/lo in regs.
// ---------------------------------------------------------------------------
__global__ __launch_bounds__(256, 2)
void scores_mma(const float* __restrict__ heads, const int* __restrict__ sid,
                int B_, int C, int O) {
    extern __shared__ float sm[];
    float* As = sm;                 // [2][128][36]
    float* Es = sm + 2 * BM * AP;   // [2][128][36]

    int tid = threadIdx.x, wid = tid >> 5, lane = tid & 31;
    int g = lane >> 2, tig = lane & 3;
    int b = blockIdx.z, o0 = blockIdx.y * BM, c0 = blockIdx.x * BN;
    int mi = (wid >> 2) * 64, ni = (wid & 3) * 32;

    // ldmatrix per-lane offsets (bytes)
    int a_row = (lane & 7) | (((lane >> 3) & 1) << 3);      // A x4: matrices (r0-7,k),(r8-15,k),(r0-7,k+4),(r8-15,k+4)
    uint32_t a_loff = (uint32_t)(a_row * AP + (lane >> 4) * 4) * 4u;
    int e_row = ((lane >> 4) << 3) + (lane & 7);            // E x4: matrices (nt even,k),(k+4),(nt odd,k),(k+4)
    uint32_t e_loff = (uint32_t)(e_row * AP + ((lane >> 3) & 1) * 4) * 4u;

    const float* hb = heads + (size_t)sid[b] * O * POS_DIM;
    const float* eb = g_emb + (size_t)b * C * POS_DIM;

    float acc[4][4][4] = {};
    const int nch = POS_DIM / BK;   // 9

    auto load = [&](int j, int buf) {
        int k0 = j * BK;
        float* A = As + buf * BM * AP;
        float* E = Es + buf * BM * AP;
        #pragma unroll
        for (int r = 0; r < 4; r++) {
            int idx = tid + r * 256;
            int m = idx >> 3, k4 = (idx & 7) * 4;
            int go = o0 + m;
            cp16(A + m * AP + k4,
                 hb + (size_t)(go < O ? go : 0) * POS_DIM + k0 + k4, go < O);
            int gc = c0 + m;
            cp16(E + m * AP + k4,
                 eb + (size_t)(gc < C ? gc : 0) * POS_DIM + k0 + k4, gc < C);
        }
        CP_COMMIT();
    };

    load(0, 0);
    for (int j = 0; j < nch; j++) {
        int buf = j & 1;
        if (j + 1 < nch) { load(j + 1, buf ^ 1); CP_WAIT1(); }
        else             { CP_WAIT0(); }
        __syncthreads();
        uint32_t Au = smem_u32(As + buf * BM * AP);
        uint32_t Eu = smem_u32(Es + buf * BM * AP);
        #pragma unroll
        for (int kk = 0; kk < BK; kk += 8) {
            uint32_t ah[4][4], al[4][4];
            #pragma unroll
            for (int mt = 0; mt < 4; mt++) {
                uint32_t raw[4];
                ldsm4(raw, Au + (uint32_t)(((mi + mt * 16) * AP + kk) * 4) + a_loff);
                #pragma unroll
                for (int q = 0; q < 4; q++) {
                    float x = __uint_as_float(raw[q]);
                    ah[mt][q] = f2tf(x);
                    al[mt][q] = f2tf(x - __uint_as_float(ah[mt][q]));
                }
            }
            #pragma unroll
            for (int p = 0; p < 2; p++) {
                uint32_t raw[4];
                ldsm4(raw, Eu + (uint32_t)(((ni + p * 16) * AP + kk) * 4) + e_loff);
                #pragma unroll
                for (int h = 0; h < 2; h++) {
                    int nt = p * 2 + h;
                    uint32_t bh[2], bl[2];
                    #pragma unroll
                    for (int q = 0; q < 2; q++) {
                        float y = __uint_as_float(raw[h * 2 + q]);
                        bh[q] = f2tf(y);
                        bl[q] = f2tf(y - __uint_as_float(bh[q]));
                    }
                    #pragma unroll
                    for (int mt = 0; mt < 4; mt++) {
                        mma8(acc[mt][nt], ah[mt], bh);
                        mma8(acc[mt][nt], ah[mt], bl);
                        mma8(acc[mt][nt], al[mt], bh);
                    }
                }
            }
        }
        __syncthreads();
    }

    float* outb = g_sc + (size_t)b * O * CP;
    #pragma unroll
    for (int mt = 0; mt < 4; mt++) {
        int r0 = o0 + mi + mt * 16 + g;
        int r1 = r0 + 8;
        #pragma unroll
        for (int nt = 0; nt < 4; nt++) {
            int gc = c0 + ni + nt * 8 + tig * 2;
            if (gc < CP) {
                if (r0 < O)
                    *(float2*)(outb + (size_t)r0 * CP + gc) =
                        make_float2(acc[mt][nt][0], acc[mt][nt][1]);
                if (r1 < O)
                    *(float2*)(outb + (size_t)r1 * CP + gc) =
                        make_float2(acc[mt][nt][2], acc[mt][nt][3]);
            }
        }
    }
}

// ---------------------------------------------------------------------------
// Kernel 3: masked softmax over C; stores tf32-PRE-ROUNDED weights (rna) so
// the out-GEMM can feed raw bits to the MMA (HW truncation = identity).
// Zero-fills cols [C, CP).
// ---------------------------------------------------------------------------
__global__ void softmax_kernel(const float* __restrict__ pos,
                               int B_, int C, int O, int rows) {
    int gwarp = (blockIdx.x * blockDim.x + threadIdx.x) >> 5;
    int lane  = threadIdx.x & 31;
    if (gwarp >= rows) return;
    int b = gwarp / O;
    float* row = g_sc + (size_t)gwarp * CP;
    const float* pb = pos + (size_t)b * C * 2;

    float v[9];
    float mx = -INFINITY;
    #pragma unroll
    for (int i = 0; i < 9; i++) {
        int c = lane + i * 32;
        float val = -INFINITY;
        if (c < C) {
            val = row[c];
            float px = pb[2 * c], py = pb[2 * c + 1];
            if (px == -0.1f && py == -0.1f) val = -INFINITY;
        }
        v[i] = val;
        mx = fmaxf(mx, val);
    }
    #pragma unroll
    for (int s = 16; s > 0; s >>= 1)
        mx = fmaxf(mx, __shfl_xor_sync(0xffffffffu, mx, s));

    float sum = 0.f;
    #pragma unroll
    for (int i = 0; i < 9; i++) {
        float e = expf(v[i] - mx);
        v[i] = e;
        sum += (lane + i * 32 < C) ? e : 0.f;
    }
    #pragma unroll
    for (int s = 16; s > 0; s >>= 1)
        sum += __shfl_xor_sync(0xffffffffu, sum, s);
    float inv = 1.f / sum;

    #pragma unroll
    for (int i = 0; i < 9; i++) {
        int c = lane + i * 32;
        if (c < C)       row[c] = __uint_as_float(f2tf(v[i] * inv));
        else if (c < CP) row[c] = 0.f;
    }
}

// ---------------------------------------------------------------------------
// Kernel 4 (dominant): out[b,o,t] = sum_c W[b,o,c] * meg[b,c,t]
// A fragments: ldmatrix.x4 on pre-rounded weights (no cvt). B: conflict-free
// scalar LDS (BP=136) + rna cvt. 9 full K-chunks.
// ---------------------------------------------------------------------------
__global__ __launch_bounds__(256, 2)
void out_mma(const float* __restrict__ meg, float* __restrict__ out,
             int B_, int C, int T, int O) {
    extern __shared__ float sm[];
    float* As = sm;                 // [2][128][36]
    float* Bs = sm + 2 * BM * AP;   // [2][32][136]

    int tid = threadIdx.x, wid = tid >> 5, lane = tid & 31;
    int g = lane >> 2, tig = lane & 3;
    int b = blockIdx.z, o0 = blockIdx.y * BM, t0 = blockIdx.x * BN;
    int mi = (wid >> 2) * 64, ni = (wid & 3) * 32;

    int a_row = (lane & 7) | (((lane >> 3) & 1) << 3);
    uint32_t a_loff = (uint32_t)(a_row * AP + (lane >> 4) * 4) * 4u;

    const float* wb = g_sc + (size_t)b * O * CP;
    const float* mb = meg  + (size_t)b * C * T;

    float acc[4][4][4] = {};
    const int nch = CP / BK;   // 9

    auto load = [&](int j, int buf) {
        int k0 = j * BK;
        float* A  = As + buf * BM * AP;
        float* Bt = Bs + buf * BK * BP;
        #pragma unroll
        for (int r = 0; r < 4; r++) {
            int idx = tid + r * 256;
            int m = idx >> 3, k4 = (idx & 7) * 4;
            int go = o0 + m;
            cp16(A + m * AP + k4,
                 wb + (size_t)(go < O ? go : 0) * CP + k0 + k4, go < O);
        }
        #pragma unroll
        for (int r = 0; r < 4; r++) {
            int idx = tid + r * 256;          // 0..1023
            int c = idx >> 5, t4 = (idx & 31) * 4;
            int gc = k0 + c;
            cp16(Bt + c * BP + t4,
                 mb + (size_t)(gc < C ? gc : 0) * T + t0 + t4, gc < C);
        }
        CP_COMMIT();
    };

    load(0, 0);
    for (int j = 0; j < nch; j++) {
        int buf = j & 1;
        if (j + 1 < nch) { load(j + 1, buf ^ 1); CP_WAIT1(); }
        else             { CP_WAIT0(); }
        __syncthreads();
        uint32_t Au = smem_u32(As + buf * BM * AP);
        const float* Bt = Bs + buf * BK * BP;
        #pragma unroll
        for (int kk = 0; kk < BK; kk += 8) {
            uint32_t a[4][4], bf[4][2];
            #pragma unroll
            for (int mt = 0; mt < 4; mt++)
                ldsm4(a[mt], Au + (uint32_t)(((mi + mt * 16) * AP + kk) * 4) + a_loff);
            #pragma unroll
            for (int nt = 0; nt < 4; nt++) {
                const float* bp = Bt + (kk + tig) * BP + ni + nt * 8 + g;
                bf[nt][0] = f2tf(bp[0]);
                bf[nt][1] = f2tf(bp[4 * BP]);
            }
            #pragma unroll
            for (int mt = 0; mt < 4; mt++)
                #pragma unroll
                for (int nt = 0; nt < 4; nt++)
                    mma8(acc[mt][nt], a[mt], bf[nt]);
        }
        __syncthreads();
    }

    #pragma unroll
    for (int mt = 0; mt < 4; mt++) {
        int r0 = o0 + mi + mt * 16 + g;
        int r1 = r0 + 8;
        #pragma unroll
        for (int nt = 0; nt < 4; nt++) {
            int col = t0 + ni + nt * 8 + tig * 2;
            if (r0 < O)
                *(float2*)(out + ((size_t)b * O + r0) * T + col) =
                    make_float2(acc[mt][nt][0], acc[mt][nt][1]);
            if (r1 < O)
                *(float2*)(out + ((size_t)b * O + r1) * T + col) =
                    make_float2(acc[mt][nt][2], acc[mt][nt][3]);
        }
    }
}

// ---------------------------------------------------------------------------
// Launch. Inputs: meg f32 [B,C,T], positions f32 [B,C,2], subject_ids i32 [B],
// heads f32 [S,O,288]. Output f32 [B,O,T].
// ---------------------------------------------------------------------------
extern "C" void kernel_launch(void* const* d_in, const int* in_sizes, int n_in,
                              void* d_out, int out_size) {
    const float* meg   = (const float*)d_in[0];
    const float* pos   = (const float*)d_in[1];
    const int*   sid   = (const int*)  d_in[2];
    const float* heads = (const float*)d_in[3];
    float* out = (float*)d_out;

    int B = in_sizes[2];
    int C = in_sizes[1] / (2 * B);
    int T = in_sizes[0] / (B * C);
    int O = out_size / (B * T);

    const int smem_sc  = 2 * BM * AP * 4 + 2 * BM * AP * 4;   // 73728 B
    const int smem_out = 2 * BM * AP * 4 + 2 * BK * BP * 4;   // 71680 B
    cudaFuncSetAttribute(scores_mma, cudaFuncAttributeMaxDynamicSharedMemorySize, smem_sc);
    cudaFuncSetAttribute(out_mma,    cudaFuncAttributeMaxDynamicSharedMemorySize, smem_out);

    // 1) Fourier embedding
    emb_kernel<<<B * C, 144>>>(pos, B * C);

    // 2) scores = heads[sid] @ emb^T  (split-tf32, ldmatrix fragments)
    dim3 gs((C + BN - 1) / BN, (O + BM - 1) / BM, B);
    scores_mma<<<gs, 256, smem_sc>>>(heads, sid, B, C, O);

    // 3) masked softmax (+ tf32 pre-round + zero pad to CP)
    int rows = B * O;
    int nblk = (rows * 32 + 255) / 256;
    softmax_kernel<<<nblk, 256>>>(pos, B, C, O, rows);

    // 4) out = weights @ meg  (tf32 mma.sync, ldmatrix A, conflict-free B)
    dim3 gd(T / BN, (O + BM - 1) / BM, B);
    out_mma<<<gd, 256, smem_out>>>(meg, out, B, C, T, O);
}

// round 8
// speedup vs baseline: 2.7884x; 1.0650x over previous
#include <cuda_runtime.h>
#include <math.h>
#include <stdint.h>

#define POS_DIM 288
#define NFREQ   12
#define CP      288      // padded pitch for weights rows (16B-aligned)
#define BM      64       // m-tile (o): 5 blocks over O=270 -> 18.5% pad (was 42%)
#define BN      128
#define BK      32
#define AP      36       // K-major smem pitch: ldmatrix + scalar reads conflict-free
#define BP      136      // meg smem pitch: 136 % 32 == 8 -> bank = 8*tig+g, bijective

// Scratch (no cudaMalloc allowed)
__device__ float g_emb[128 * 273 * 288];   // [B*C, 288]
__device__ float g_sc [128 * 270 * CP];    // [B, O, CP] scores -> tf32-rounded weights

// ---------------------------------------------------------------------------
// helpers
// ---------------------------------------------------------------------------
__device__ __forceinline__ uint32_t smem_u32(const void* p) {
    uint32_t a;
    asm("{ .reg .u64 t; cvta.to.shared.u64 t, %1; cvt.u32.u64 %0, t; }"
        : "=r"(a) : "l"(p));
    return a;
}
__device__ __forceinline__ void cp16(const void* dst, const void* src, bool full) {
    uint32_t d = smem_u32(dst);
    int sz = full ? 16 : 0;
    asm volatile("cp.async.cg.shared.global [%0], [%1], 16, %2;"
                 :: "r"(d), "l"(src), "r"(sz) : "memory");
}
#define CP_COMMIT() asm volatile("cp.async.commit_group;" ::: "memory")
#define CP_WAIT1()  asm volatile("cp.async.wait_group 1;" ::: "memory")
#define CP_WAIT0()  asm volatile("cp.async.wait_group 0;" ::: "memory")

__device__ __forceinline__ uint32_t f2tf(float x) {   // round-to-nearest tf32
    uint32_t r;
    asm("cvt.rna.tf32.f32 %0, %1;" : "=r"(r) : "f"(x));
    return r;
}
__device__ __forceinline__ void ldsm4(uint32_t r[4], uint32_t addr) {
    asm volatile("ldmatrix.sync.aligned.m8n8.x4.shared.b16 {%0,%1,%2,%3}, [%4];"
                 : "=r"(r[0]), "=r"(r[1]), "=r"(r[2]), "=r"(r[3]) : "r"(addr));
}
__device__ __forceinline__ void mma8(float c[4], const uint32_t a[4], const uint32_t b[2]) {
    asm volatile(
        "mma.sync.aligned.m16n8k8.row.col.f32.tf32.tf32.f32 "
        "{%0,%1,%2,%3}, {%4,%5,%6,%7}, {%8,%9}, {%0,%1,%2,%3};"
        : "+f"(c[0]), "+f"(c[1]), "+f"(c[2]), "+f"(c[3])
        : "r"(a[0]), "r"(a[1]), "r"(a[2]), "r"(a[3]), "r"(b[0]), "r"(b[1]));
}

// ---------------------------------------------------------------------------
// Kernel 1: Fourier embedding
// ---------------------------------------------------------------------------
__global__ void emb_kernel(const float* __restrict__ pos, int BC) {
    int row = blockIdx.x;
    if (row >= BC) return;
    int j = threadIdx.x;                    // 0..143
    float px = pos[2 * row]     + 0.2f;
    float py = pos[2 * row + 1] + 0.2f;
    const float w = 6.283185307179586f / 1.4f;
    int fi = j / NFREQ;
    int fj = j - fi * NFREQ;
    float loc = px * (w * (float)fi) + py * (w * (float)fj);
    float s, c;
    sincosf(loc, &s, &c);
    size_t base = (size_t)row * POS_DIM;
    g_emb[base + j]       = c;
    g_emb[base + 144 + j] = s;
}

// ---------------------------------------------------------------------------
// Kernel 2: scores[b,o,c] = sum_d heads[sid[b],o,d] * emb[b,c,d]
// Split-tf32 (hi/lo, 3 MMAs). BM=64: warp tile 32(o) x 32(c).
// ---------------------------------------------------------------------------
__global__ __launch_bounds__(256, 2)
void scores_mma(const float* __restrict__ heads, const int* __restrict__ sid,
                int B_, int C, int O) {
    extern __shared__ float sm[];
    float* As = sm;                 // [2][64][36]
    float* Es = sm + 2 * BM * AP;   // [2][128][36]

    int tid = threadIdx.x, wid = tid >> 5, lane = tid & 31;
    int g = lane >> 2, tig = lane & 3;
    int b = blockIdx.z, o0 = blockIdx.y * BM, c0 = blockIdx.x * BN;
    int mi = (wid >> 2) * 32, ni = (wid & 3) * 32;

    // ldmatrix per-lane offsets (bytes)
    int a_row = (lane & 7) | (((lane >> 3) & 1) << 3);
    uint32_t a_loff = (uint32_t)(a_row * AP + (lane >> 4) * 4) * 4u;
    int e_row = ((lane >> 4) << 3) + (lane & 7);
    uint32_t e_loff = (uint32_t)(e_row * AP + ((lane >> 3) & 1) * 4) * 4u;

    const float* hb = heads + (size_t)sid[b] * O * POS_DIM;
    const float* eb = g_emb + (size_t)b * C * POS_DIM;

    float acc[2][4][4] = {};
    const int nch = POS_DIM / BK;   // 9

    auto load = [&](int j, int buf) {
        int k0 = j * BK;
        float* A = As + buf * BM * AP;
        float* E = Es + buf * BN * AP;
        #pragma unroll
        for (int r = 0; r < 2; r++) {          // A: 64 x 32 = 512 cp16
            int idx = tid + r * 256;
            int m = idx >> 3, k4 = (idx & 7) * 4;
            int go = o0 + m;
            cp16(A + m * AP + k4,
                 hb + (size_t)(go < O ? go : 0) * POS_DIM + k0 + k4, go < O);
        }
        #pragma unroll
        for (int r = 0; r < 4; r++) {          // E: 128 x 32 = 1024 cp16
            int idx = tid + r * 256;
            int m = idx >> 3, k4 = (idx & 7) * 4;
            int gc = c0 + m;
            cp16(E + m * AP + k4,
                 eb + (size_t)(gc < C ? gc : 0) * POS_DIM + k0 + k4, gc < C);
        }
        CP_COMMIT();
    };

    load(0, 0);
    for (int j = 0; j < nch; j++) {
        int buf = j & 1;
        if (j + 1 < nch) { load(j + 1, buf ^ 1); CP_WAIT1(); }
        else             { CP_WAIT0(); }
        __syncthreads();
        uint32_t Au = smem_u32(As + buf * BM * AP);
        uint32_t Eu = smem_u32(Es + buf * BN * AP);
        #pragma unroll
        for (int kk = 0; kk < BK; kk += 8) {
            uint32_t ah[2][4], al[2][4];
            #pragma unroll
            for (int mt = 0; mt < 2; mt++) {
                uint32_t raw[4];
                ldsm4(raw, Au + (uint32_t)(((mi + mt * 16) * AP + kk) * 4) + a_loff);
                #pragma unroll
                for (int q = 0; q < 4; q++) {
                    float x = __uint_as_float(raw[q]);
                    ah[mt][q] = f2tf(x);
                    al[mt][q] = f2tf(x - __uint_as_float(ah[mt][q]));
                }
            }
            #pragma unroll
            for (int p = 0; p < 2; p++) {
                uint32_t raw[4];
                ldsm4(raw, Eu + (uint32_t)(((ni + p * 16) * AP + kk) * 4) + e_loff);
                #pragma unroll
                for (int h = 0; h < 2; h++) {
                    int nt = p * 2 + h;
                    uint32_t bh[2], bl[2];
                    #pragma unroll
                    for (int q = 0; q < 2; q++) {
                        float y = __uint_as_float(raw[h * 2 + q]);
                        bh[q] = f2tf(y);
                        bl[q] = f2tf(y - __uint_as_float(bh[q]));
                    }
                    #pragma unroll
                    for (int mt = 0; mt < 2; mt++) {
                        mma8(acc[mt][nt], ah[mt], bh);
                        mma8(acc[mt][nt], ah[mt], bl);
                        mma8(acc[mt][nt], al[mt], bh);
                    }
                }
            }
        }
        __syncthreads();
    }

    float* outb = g_sc + (size_t)b * O * CP;
    #pragma unroll
    for (int mt = 0; mt < 2; mt++) {
        int r0 = o0 + mi + mt * 16 + g;
        int r1 = r0 + 8;
        #pragma unroll
        for (int nt = 0; nt < 4; nt++) {
            int gc = c0 + ni + nt * 8 + tig * 2;
            if (gc < CP) {
                if (r0 < O)
                    *(float2*)(outb + (size_t)r0 * CP + gc) =
                        make_float2(acc[mt][nt][0], acc[mt][nt][1]);
                if (r1 < O)
                    *(float2*)(outb + (size_t)r1 * CP + gc) =
                        make_float2(acc[mt][nt][2], acc[mt][nt][3]);
            }
        }
    }
}

// ---------------------------------------------------------------------------
// Kernel 3: masked softmax over C; stores tf32-pre-rounded weights so the
// out-GEMM feeds raw bits to the MMA (HW truncation = identity).
// Zero-fills cols [C, CP).
// ---------------------------------------------------------------------------
__global__ void softmax_kernel(const float* __restrict__ pos,
                               int B_, int C, int O, int rows) {
    int gwarp = (blockIdx.x * blockDim.x + threadIdx.x) >> 5;
    int lane  = threadIdx.x & 31;
    if (gwarp >= rows) return;
    int b = gwarp / O;
    float* row = g_sc + (size_t)gwarp * CP;
    const float* pb = pos + (size_t)b * C * 2;

    float v[9];
    float mx = -INFINITY;
    #pragma unroll
    for (int i = 0; i < 9; i++) {
        int c = lane + i * 32;
        float val = -INFINITY;
        if (c < C) {
            val = row[c];
            float px = pb[2 * c], py = pb[2 * c + 1];
            if (px == -0.1f && py == -0.1f) val = -INFINITY;
        }
        v[i] = val;
        mx = fmaxf(mx, val);
    }
    #pragma unroll
    for (int s = 16; s > 0; s >>= 1)
        mx = fmaxf(mx, __shfl_xor_sync(0xffffffffu, mx, s));

    float sum = 0.f;
    #pragma unroll
    for (int i = 0; i < 9; i++) {
        float e = expf(v[i] - mx);
        v[i] = e;
        sum += (lane + i * 32 < C) ? e : 0.f;
    }
    #pragma unroll
    for (int s = 16; s > 0; s >>= 1)
        sum += __shfl_xor_sync(0xffffffffu, sum, s);
    float inv = 1.f / sum;

    #pragma unroll
    for (int i = 0; i < 9; i++) {
        int c = lane + i * 32;
        if (c < C)       row[c] = __uint_as_float(f2tf(v[i] * inv));
        else if (c < CP) row[c] = 0.f;
    }
}

// ---------------------------------------------------------------------------
// Kernel 4 (dominant): out[b,o,t] = sum_c W[b,o,c] * meg[b,c,t]
// BM=64 warp tile 32(o) x 32(t); 3 CTAs/SM via launch_bounds. ldmatrix A
// (pre-rounded weights, no cvt), conflict-free scalar B LDS + rna cvt.
// ---------------------------------------------------------------------------
__global__ __launch_bounds__(256, 3)
void out_mma(const float* __restrict__ meg, float* __restrict__ out,
             int B_, int C, int T, int O) {
    extern __shared__ float sm[];
    float* As = sm;                 // [2][64][36]
    float* Bs = sm + 2 * BM * AP;   // [2][32][136]

    int tid = threadIdx.x, wid = tid >> 5, lane = tid & 31;
    int g = lane >> 2, tig = lane & 3;
    int b = blockIdx.z, o0 = blockIdx.y * BM, t0 = blockIdx.x * BN;
    int mi = (wid >> 2) * 32, ni = (wid & 3) * 32;

    int a_row = (lane & 7) | (((lane >> 3) & 1) << 3);
    uint32_t a_loff = (uint32_t)(a_row * AP + (lane >> 4) * 4) * 4u;

    const float* wb = g_sc + (size_t)b * O * CP;
    const float* mb = meg  + (size_t)b * C * T;

    float acc[2][4][4] = {};
    const int nch = CP / BK;   // 9

    auto load = [&](int j, int buf) {
        int k0 = j * BK;
        float* A  = As + buf * BM * AP;
        float* Bt = Bs + buf * BK * BP;
        #pragma unroll
        for (int r = 0; r < 2; r++) {          // A: 64 x 32 = 512 cp16
            int idx = tid + r * 256;
            int m = idx >> 3, k4 = (idx & 7) * 4;
            int go = o0 + m;
            cp16(A + m * AP + k4,
                 wb + (size_t)(go < O ? go : 0) * CP + k0 + k4, go < O);
        }
        #pragma unroll
        for (int r = 0; r < 4; r++) {          // B: 32 x 128 = 1024 cp16
            int idx = tid + r * 256;
            int c = idx >> 5, t4 = (idx & 31) * 4;
            int gc = k0 + c;
            cp16(Bt + c * BP + t4,
                 mb + (size_t)(gc < C ? gc : 0) * T + t0 + t4, gc < C);
        }
        CP_COMMIT();
    };

    load(0, 0);
    for (int j = 0; j < nch; j++) {
        int buf = j & 1;
        if (j + 1 < nch) { load(j + 1, buf ^ 1); CP_WAIT1(); }
        else             { CP_WAIT0(); }
        __syncthreads();
        uint32_t Au = smem_u32(As + buf * BM * AP);
        const float* Bt = Bs + buf * BK * BP;
        #pragma unroll
        for (int kk = 0; kk < BK; kk += 8) {
            uint32_t a[2][4], bf[4][2];
            #pragma unroll
            for (int mt = 0; mt < 2; mt++)
                ldsm4(a[mt], Au + (uint32_t)(((mi + mt * 16) * AP + kk) * 4) + a_loff);
            #pragma unroll
            for (int nt = 0; nt < 4; nt++) {
                const float* bp = Bt + (kk + tig) * BP + ni + nt * 8 + g;
                bf[nt][0] = f2tf(bp[0]);
                bf[nt][1] = f2tf(bp[4 * BP]);
            }
            #pragma unroll
            for (int mt = 0; mt < 2; mt++)
                #pragma unroll
                for (int nt = 0; nt < 4; nt++)
                    mma8(acc[mt][nt], a[mt], bf[nt]);
        }
        __syncthreads();
    }

    #pragma unroll
    for (int mt = 0; mt < 2; mt++) {
        int r0 = o0 + mi + mt * 16 + g;
        int r1 = r0 + 8;
        #pragma unroll
        for (int nt = 0; nt < 4; nt++) {
            int col = t0 + ni + nt * 8 + tig * 2;
            if (r0 < O)
                *(float2*)(out + ((size_t)b * O + r0) * T + col) =
                    make_float2(acc[mt][nt][0], acc[mt][nt][1]);
            if (r1 < O)
                *(float2*)(out + ((size_t)b * O + r1) * T + col) =
                    make_float2(acc[mt][nt][2], acc[mt][nt][3]);
        }
    }
}

// ---------------------------------------------------------------------------
// Launch. Inputs: meg f32 [B,C,T], positions f32 [B,C,2], subject_ids i32 [B],
// heads f32 [S,O,288]. Output f32 [B,O,T].
// ---------------------------------------------------------------------------
extern "C" void kernel_launch(void* const* d_in, const int* in_sizes, int n_in,
                              void* d_out, int out_size) {
    const float* meg   = (const float*)d_in[0];
    const float* pos   = (const float*)d_in[1];
    const int*   sid   = (const int*)  d_in[2];
    const float* heads = (const float*)d_in[3];
    float* out = (float*)d_out;

    int B = in_sizes[2];
    int C = in_sizes[1] / (2 * B);
    int T = in_sizes[0] / (B * C);
    int O = out_size / (B * T);

    const int smem_sc  = 2 * BM * AP * 4 + 2 * BN * AP * 4;   // 55296 B
    const int smem_out = 2 * BM * AP * 4 + 2 * BK * BP * 4;   // 53248 B
    cudaFuncSetAttribute(scores_mma, cudaFuncAttributeMaxDynamicSharedMemorySize, smem_sc);
    cudaFuncSetAttribute(out_mma,    cudaFuncAttributeMaxDynamicSharedMemorySize, smem_out);

    // 1) Fourier embedding
    emb_kernel<<<B * C, 144>>>(pos, B * C);

    // 2) scores = heads[sid] @ emb^T  (split-tf32, ldmatrix fragments)
    dim3 gs((C + BN - 1) / BN, (O + BM - 1) / BM, B);
    scores_mma<<<gs, 256, smem_sc>>>(heads, sid, B, C, O);

    // 3) masked softmax (+ tf32 pre-round + zero pad to CP)
    int rows = B * O;
    int nblk = (rows * 32 + 255) / 256;
    softmax_kernel<<<nblk, 256>>>(pos, B, C, O, rows);

    // 4) out = weights @ meg  (tf32 mma.sync, ldmatrix A, conflict-free B)
    dim3 gd(T / BN, (O + BM - 1) / BM, B);
    out_mma<<<gd, 256, smem_out>>>(meg, out, B, C, T, O);
}